// round 9
// baseline (speedup 1.0000x reference)
#include <cuda_runtime.h>
#include <cstdint>

// Fixed problem shape: B=4, H=W=256, DIM=192, NH=6, HD=32, WS=8
// Pre-permuted / tf32-rounded weights
__device__ float g_wqh[110592];   // [6][96][192]  rows = [q(32)|k(32)|v(32)] of head h
__device__ float g_bqh[576];      // [6][96]
__device__ float g_woh[36864];    // [6][192][32]  woh[h][n][k] = out_w[n][h*32+k]

// ======================= helpers =======================
__device__ __forceinline__ uint32_t smem_u32(const void* p) {
    uint32_t a;
    asm("{ .reg .u64 t; cvta.to.shared.u64 t, %1; cvt.u32.u64 %0, t; }" : "=r"(a) : "l"(p));
    return a;
}
__device__ __forceinline__ void cp_async16(uint32_t dst, const void* src) {
    asm volatile("cp.async.cg.shared.global [%0], [%1], 16;" :: "r"(dst), "l"(src));
}
#define CP_COMMIT() asm volatile("cp.async.commit_group;" ::: "memory")
#define CP_WAIT1()  asm volatile("cp.async.wait_group 1;" ::: "memory")

__device__ __forceinline__ uint32_t to_tf32(float f) {
    uint32_t r;
    asm("cvt.rna.tf32.f32 %0, %1;" : "=r"(r) : "f"(f));
    return r;
}
__device__ __forceinline__ void mma_tf32(float* c, const uint32_t* a, uint32_t b0, uint32_t b1) {
    asm volatile(
        "mma.sync.aligned.m16n8k8.row.col.f32.tf32.tf32.f32 "
        "{%0,%1,%2,%3}, {%4,%5,%6,%7}, {%8,%9}, {%0,%1,%2,%3};"
        : "+f"(c[0]), "+f"(c[1]), "+f"(c[2]), "+f"(c[3])
        : "r"(a[0]), "r"(a[1]), "r"(a[2]), "r"(a[3]), "r"(b0), "r"(b1));
}

// ======================= weight pre-permute + tf32 round =======================
__global__ void wconv_kernel(const float* __restrict__ qkv_w, const float* __restrict__ qkv_b,
                             const float* __restrict__ out_w,
                             float* __restrict__ wqh, float* __restrict__ bqh,
                             float* __restrict__ woh) {
    int i0 = blockIdx.x * blockDim.x + threadIdx.x;
    int stride = gridDim.x * blockDim.x;
    for (int idx = i0; idx < 110592; idx += stride) {
        int h = idx / (96 * 192), rem = idx % (96 * 192);
        int j = rem / 192, k = rem % 192;
        int src = (j < 32) ? (h * 32 + j) : (j < 64) ? (192 + h * 32 + j - 32) : (384 + h * 32 + j - 64);
        wqh[idx] = __uint_as_float(to_tf32(qkv_w[src * 192 + k]));
    }
    for (int idx = i0; idx < 576; idx += stride) {
        int h = idx / 96, j = idx % 96;
        int src = (j < 32) ? (h * 32 + j) : (j < 64) ? (192 + h * 32 + j - 32) : (384 + h * 32 + j - 64);
        bqh[idx] = qkv_b[src];
    }
    for (int idx = i0; idx < 36864; idx += stride) {
        int h = idx / (192 * 32), rem = idx % (192 * 32);
        int n = rem / 32, k = rem % 32;
        woh[idx] = __uint_as_float(to_tf32(out_w[n * 192 + h * 32 + k]));
    }
}

// ======================= fully fused window kernel =======================
// one CTA = one window (64 tokens). 512 threads = 16 warps (4m x 4n).
// smem floats: sX 64x196 | sW 2x96x36 | sQK 64x68 | sVt 32x68 | sP 64x68 | sO 64x36 | sOW 192x36 | sPE 32x12 | sPEb 32
static const int FUSED_SMEM = (12544 + 6912 + 4352 + 2176 + 4352 + 2304 + 6912 + 384 + 32) * 4;  // 159,872 B

__global__ __launch_bounds__(512, 1) void fused_kernel(
    const float* __restrict__ x,
    const float* __restrict__ wqh, const float* __restrict__ bqh,
    const float* __restrict__ woh,
    const float* __restrict__ pe_w, const float* __restrict__ pe_b,
    const float* __restrict__ out_b, float* __restrict__ out)
{
    extern __shared__ float sm[];
    float* sX  = sm;            // 12544
    float* sW  = sX + 12544;    // 6912
    float* sQK = sW + 6912;     // 4352
    float* sVt = sQK + 4352;    // 2176
    float* sP  = sVt + 2176;    // 4352
    float* sO  = sP + 4352;     // 2304
    float* sOW = sO + 2304;     // 6912
    float* sPE = sOW + 6912;    // 384
    float* sPEb = sPE + 384;    // 32

    const uint32_t uX = smem_u32(sX), uW = smem_u32(sW), uOW = smem_u32(sOW);

    const int tid = threadIdx.x;
    const int wid = tid >> 5, lane = tid & 31;
    const int wm = wid & 3, wn = wid >> 2;
    const int g = lane >> 2, tg = lane & 3;

    const int w = blockIdx.x;
    const int bb = w >> 10;
    const int wy = (w & 1023) >> 5, wx = w & 31;

    float outacc[6][4];
#pragma unroll
    for (int i = 0; i < 6; i++)
#pragma unroll
        for (int j = 0; j < 4; j++) outacc[i][j] = 0.f;

    const int r0 = wm * 16 + g;   // m row within window (0..63), +8 for second

    for (int h = 0; h < 6; h++) {
        // ---- issue async loads: [x tile (h==0) + out_w slice] , chunk0, chunk1 ----
        if (h == 0) {
#pragma unroll
            for (int i = 0; i < 6; i++) {
                int idx = tid + i * 512;           // 3072 float4
                int t = idx / 48, c4 = idx % 48;
                int n = (wy * 8 + (t >> 3)) * 256 + wx * 8 + (t & 7);
                cp_async16(uX + (t * 196 + c4 * 4) * 4,
                           &x[((size_t)(bb * 65536 + n)) * 192 + c4 * 4]);
            }
        }
#pragma unroll
        for (int i = 0; i < 3; i++) {              // sOW: 1536 float4
            int idx = tid + i * 512;
            int row = idx >> 3, c4 = idx & 7;
            cp_async16(uOW + (row * 36 + c4 * 4) * 4,
                       &woh[((size_t)(h * 192 + row)) * 32 + c4 * 4]);
        }
        CP_COMMIT();
        // chunk loader: 96 rows x 8 float4 = 768
#pragma unroll
        for (int pc = 0; pc < 2; pc++) {
#pragma unroll
            for (int i = 0; i < 2; i++) {
                int idx = tid + i * 512;
                if (idx < 768) {
                    int row = idx >> 3, c4 = idx & 7;
                    cp_async16(uW + (pc * 3456 + row * 36 + c4 * 4) * 4,
                               &wqh[((size_t)(h * 96 + row)) * 192 + pc * 32 + c4 * 4]);
                }
            }
            CP_COMMIT();
        }

        // ---- Phase A: QKV head-gemm  C(64x96) = X(64x192) @ Wh(96x192)^T ----
        float acc[3][4];
#pragma unroll
        for (int i = 0; i < 3; i++)
#pragma unroll
            for (int j = 0; j < 4; j++) acc[i][j] = 0.f;

        for (int kc = 0; kc < 6; kc++) {
            CP_WAIT1();
            __syncthreads();
            const float* Wb = sW + (kc & 1) * 3456;
#pragma unroll
            for (int ks = 0; ks < 4; ks++) {
                const int k0 = kc * 32 + ks * 8;
                const int kw = ks * 8;
                uint32_t a[4];
                a[0] = to_tf32(sX[r0 * 196 + k0 + tg]);
                a[1] = to_tf32(sX[(r0 + 8) * 196 + k0 + tg]);
                a[2] = to_tf32(sX[r0 * 196 + k0 + tg + 4]);
                a[3] = to_tf32(sX[(r0 + 8) * 196 + k0 + tg + 4]);
#pragma unroll
                for (int nt = 0; nt < 3; nt++) {
                    int n0 = wn * 24 + nt * 8 + g;
                    uint32_t b0 = __float_as_uint(Wb[n0 * 36 + kw + tg]);
                    uint32_t b1 = __float_as_uint(Wb[n0 * 36 + kw + tg + 4]);
                    mma_tf32(acc[nt], a, b0, b1);
                }
            }
            __syncthreads();
            if (kc + 2 < 6) {
#pragma unroll
                for (int i = 0; i < 2; i++) {
                    int idx = tid + i * 512;
                    if (idx < 768) {
                        int row = idx >> 3, c4 = idx & 7;
                        cp_async16(uW + ((kc & 1) * 3456 + row * 36 + c4 * 4) * 4,
                                   &wqh[((size_t)(h * 96 + row)) * 192 + (kc + 2) * 32 + c4 * 4]);
                    }
                }
            }
            CP_COMMIT();
        }

        // Phase A epilogue: scatter q,k -> sQK[t][0..63], v -> sVt[d][t]
#pragma unroll
        for (int nt = 0; nt < 3; nt++) {
            int c = wn * 24 + nt * 8 + tg * 2;
            float b0v = bqh[h * 96 + c], b1v = bqh[h * 96 + c + 1];
            float v00 = acc[nt][0] + b0v, v01 = acc[nt][1] + b1v;
            float v10 = acc[nt][2] + b0v, v11 = acc[nt][3] + b1v;
            if (c < 64) {
                sQK[r0 * 68 + c] = v00;       sQK[r0 * 68 + c + 1] = v01;
                sQK[(r0 + 8) * 68 + c] = v10; sQK[(r0 + 8) * 68 + c + 1] = v11;
            } else {
                int d = c - 64;
                sVt[d * 68 + r0] = v00;       sVt[(d + 1) * 68 + r0] = v01;
                sVt[d * 68 + r0 + 8] = v10;   sVt[(d + 1) * 68 + r0 + 8] = v11;
            }
        }
        // pe weights for this head
        if (tid < 288) sPE[(tid / 9) * 12 + tid % 9] = pe_w[(h * 32 + tid / 9) * 9 + tid % 9];
        if (tid >= 480) sPEb[tid - 480] = pe_b[h * 32 + tid - 480];
        __syncthreads();

        // ---- Phase B: logits(64x64) = q @ k^T ----
        {
            float bacc[2][4];
#pragma unroll
            for (int i = 0; i < 2; i++)
#pragma unroll
                for (int j = 0; j < 4; j++) bacc[i][j] = 0.f;
#pragma unroll
            for (int ks = 0; ks < 4; ks++) {
                const int k0 = ks * 8;
                uint32_t a[4];
                a[0] = to_tf32(sQK[r0 * 68 + k0 + tg]);
                a[1] = to_tf32(sQK[(r0 + 8) * 68 + k0 + tg]);
                a[2] = to_tf32(sQK[r0 * 68 + k0 + tg + 4]);
                a[3] = to_tf32(sQK[(r0 + 8) * 68 + k0 + tg + 4]);
#pragma unroll
                for (int nt = 0; nt < 2; nt++) {
                    int n0 = wn * 16 + nt * 8 + g;
                    uint32_t b0 = to_tf32(sQK[n0 * 68 + 32 + k0 + tg]);
                    uint32_t b1 = to_tf32(sQK[n0 * 68 + 32 + k0 + tg + 4]);
                    mma_tf32(bacc[nt], a, b0, b1);
                }
            }
            const float scale = 0.17677669529663687f;
#pragma unroll
            for (int nt = 0; nt < 2; nt++) {
                int s = wn * 16 + nt * 8 + tg * 2;
                sP[r0 * 68 + s] = bacc[nt][0] * scale;
                sP[r0 * 68 + s + 1] = bacc[nt][1] * scale;
                sP[(r0 + 8) * 68 + s] = bacc[nt][2] * scale;
                sP[(r0 + 8) * 68 + s + 1] = bacc[nt][3] * scale;
            }
        }
        __syncthreads();

        // ---- Phase C: softmax over s (8 threads per row) ----
        {
            int t = tid >> 3, q = tid & 7;
            float* row = sP + t * 68 + q * 8;
            float4 x0 = *(float4*)row;
            float4 x1 = *(float4*)(row + 4);
            float m = fmaxf(fmaxf(fmaxf(x0.x, x0.y), fmaxf(x0.z, x0.w)),
                            fmaxf(fmaxf(x1.x, x1.y), fmaxf(x1.z, x1.w)));
            m = fmaxf(m, __shfl_xor_sync(0xffffffffu, m, 1));
            m = fmaxf(m, __shfl_xor_sync(0xffffffffu, m, 2));
            m = fmaxf(m, __shfl_xor_sync(0xffffffffu, m, 4));
            float e0 = __expf(x0.x - m), e1 = __expf(x0.y - m), e2 = __expf(x0.z - m), e3 = __expf(x0.w - m);
            float e4 = __expf(x1.x - m), e5 = __expf(x1.y - m), e6 = __expf(x1.z - m), e7 = __expf(x1.w - m);
            float s = e0 + e1 + e2 + e3 + e4 + e5 + e6 + e7;
            s += __shfl_xor_sync(0xffffffffu, s, 1);
            s += __shfl_xor_sync(0xffffffffu, s, 2);
            s += __shfl_xor_sync(0xffffffffu, s, 4);
            float inv = 1.0f / s;
            *(float4*)row       = make_float4(e0 * inv, e1 * inv, e2 * inv, e3 * inv);
            *(float4*)(row + 4) = make_float4(e4 * inv, e5 * inv, e6 * inv, e7 * inv);
        }
        __syncthreads();

        // ---- Phase D: o(64x32) = P(64x64) @ v(64x32) ----
        {
            float dacc[4] = {0.f, 0.f, 0.f, 0.f};
            const int n0 = wn * 8 + g;
#pragma unroll
            for (int ks = 0; ks < 8; ks++) {
                const int k0 = ks * 8;
                uint32_t a[4];
                a[0] = to_tf32(sP[r0 * 68 + k0 + tg]);
                a[1] = to_tf32(sP[(r0 + 8) * 68 + k0 + tg]);
                a[2] = to_tf32(sP[r0 * 68 + k0 + tg + 4]);
                a[3] = to_tf32(sP[(r0 + 8) * 68 + k0 + tg + 4]);
                uint32_t b0 = to_tf32(sVt[n0 * 68 + k0 + tg]);
                uint32_t b1 = to_tf32(sVt[n0 * 68 + k0 + tg + 4]);
                mma_tf32(dacc, a, b0, b1);
            }
            int d = wn * 8 + tg * 2;
            sO[r0 * 36 + d] = dacc[0];       sO[r0 * 36 + d + 1] = dacc[1];
            sO[(r0 + 8) * 36 + d] = dacc[2]; sO[(r0 + 8) * 36 + d + 1] = dacc[3];
        }
        __syncthreads();

        // ---- Phase E: LePE (depthwise 3x3 over 8x8 window, per d channel) ----
#pragma unroll
        for (int i = tid; i < 2048; i += 512) {
            int t = i >> 5, d = i & 31;
            int ty = t >> 3, tx = t & 7;
            float l = sPEb[d];
#pragma unroll
            for (int ky = 0; ky < 3; ky++) {
                int yy = ty + ky - 1;
                if (yy < 0 || yy > 7) continue;
#pragma unroll
                for (int kx = 0; kx < 3; kx++) {
                    int xx = tx + kx - 1;
                    if (xx < 0 || xx > 7) continue;
                    l += sPE[d * 12 + ky * 3 + kx] * sVt[d * 68 + yy * 8 + xx];
                }
            }
            sO[t * 36 + d] += l;
        }
        __syncthreads();

        // ---- Phase F: out(64x192) += o(64x32) @ woh[h](192x32)^T ----
#pragma unroll
        for (int ks = 0; ks < 4; ks++) {
            const int k0 = ks * 8;
            uint32_t a[4];
            a[0] = to_tf32(sO[r0 * 36 + k0 + tg]);
            a[1] = to_tf32(sO[(r0 + 8) * 36 + k0 + tg]);
            a[2] = to_tf32(sO[r0 * 36 + k0 + tg + 4]);
            a[3] = to_tf32(sO[(r0 + 8) * 36 + k0 + tg + 4]);
#pragma unroll
            for (int nt = 0; nt < 6; nt++) {
                int n0 = wn * 48 + nt * 8 + g;
                uint32_t b0 = __float_as_uint(sOW[n0 * 36 + k0 + tg]);
                uint32_t b1 = __float_as_uint(sOW[n0 * 36 + k0 + tg + 4]);
                mma_tf32(outacc[nt], a, b0, b1);
            }
        }
        __syncthreads();   // protect sQK/sVt/sOW before next head's writes
    }

    // ---- final epilogue: + out_b, store to (B, N, C) ----
    const int n0g = (wy * 8 + (r0 >> 3)) * 256 + wx * 8 + (r0 & 7);
    const int r1 = r0 + 8;
    const int n1g = (wy * 8 + (r1 >> 3)) * 256 + wx * 8 + (r1 & 7);
    const size_t base0 = ((size_t)(bb * 65536 + n0g)) * 192;
    const size_t base1 = ((size_t)(bb * 65536 + n1g)) * 192;
#pragma unroll
    for (int nt = 0; nt < 6; nt++) {
        int col = wn * 48 + nt * 8 + tg * 2;
        float2 ob = *(const float2*)&out_b[col];
        *(float2*)&out[base0 + col] = make_float2(outacc[nt][0] + ob.x, outacc[nt][1] + ob.y);
        *(float2*)&out[base1 + col] = make_float2(outacc[nt][2] + ob.x, outacc[nt][3] + ob.y);
    }
}

// ======================= launcher =======================
extern "C" void kernel_launch(void* const* d_in, const int* in_sizes, int n_in,
                              void* d_out, int out_size) {
    const float* x     = (const float*)d_in[0];
    const float* qkv_w = (const float*)d_in[1];
    const float* qkv_b = (const float*)d_in[2];
    const float* pe_w  = (const float*)d_in[3];
    const float* pe_b  = (const float*)d_in[4];
    const float* out_w = (const float*)d_in[5];
    const float* out_b = (const float*)d_in[6];
    float* out = (float*)d_out;

    const int B = in_sizes[0] / (65536 * 192);

    float *wqh_s, *bqh_s, *woh_s;
    cudaGetSymbolAddress((void**)&wqh_s, g_wqh);
    cudaGetSymbolAddress((void**)&bqh_s, g_bqh);
    cudaGetSymbolAddress((void**)&woh_s, g_woh);

    static bool attr_set = false;
    if (!attr_set) {
        cudaFuncSetAttribute(fused_kernel, cudaFuncAttributeMaxDynamicSharedMemorySize, FUSED_SMEM);
        attr_set = true;
    }

    wconv_kernel<<<144, 256>>>(qkv_w, qkv_b, out_w, wqh_s, bqh_s, woh_s);

    fused_kernel<<<B * 1024, 512, FUSED_SMEM>>>(
        x, wqh_s, bqh_s, woh_s, pe_w, pe_b, out_b, out);
}